// round 5
// baseline (speedup 1.0000x reference)
#include <cuda_runtime.h>
#include <math.h>

#define RF   1024
#define US   200
#define MGC  60
#define FS   64
#define NS   4
#define NL   10
#define NWIN 1600
#define VSCALE 0.70710678118f

// Scratch (device globals: no allocation allowed)
__device__ float g_prevx[RF + NWIN];
__device__ float g_new[NWIN];
__device__ float g_cond[NWIN * MGC];

// ---------------- prep kernels ----------------
__global__ void k_copy(const float* __restrict__ noise) {
    int i = blockIdx.x * blockDim.x + threadIdx.x;
    if (i < RF + NWIN) g_prevx[i] = noise[i];
}

__global__ void k_cond(const float* __restrict__ mgc,
                       const float* __restrict__ cond_w,
                       const float* __restrict__ cond_b) {
    int n = blockIdx.x;
    int m = threadIdx.x;
    if (m >= MGC) return;
    int f = n / US, u = n % US;
    int r = u * MGC + m;
    const float* wrow = cond_w + (size_t)r * MGC;
    const float* mrow = mgc + f * MGC;
    float acc = cond_b[r];
#pragma unroll
    for (int k = 0; k < MGC; k++) acc += mrow[k] * wrow[k];
    g_cond[n * MGC + m] = tanhf(acc);
}

// ---------------- per-stage kernel: one CTA = one window ----------------
// smem layout (floats):
//   xwin  [1024]
//   condv [64]
//   cproj [NL*2*64 = 1280]
//   wbuf  [3*16*128 = 6144]   (l=1,2 weight blocks, layer0 weights, reduction)
//   bufA  [64*512 = 32768]    (tail bufA+8192.. doubles as full-layer weights for l>=3)
//   bufB  [64*256 = 16384]
#define SM_XWIN  0
#define SM_COND  1024
#define SM_CPROJ 1088
#define SM_WBUF  2368
#define SM_BUFA  8512
#define SM_BUFB  41280
#define SM_FLOATS (41280 + 16384)
#define SMEM_BYTES (SM_FLOATS * 4)

__device__ __forceinline__ float sigmoidf_(float v) {
    return 1.0f / (1.0f + expf(-v));
}

__global__ __launch_bounds__(512, 1) void k_stage(
    int s,
    const float* __restrict__ conv0_w, const float* __restrict__ convs_w,
    const float* __restrict__ conv_b,
    const float* __restrict__ ccw, const float* __restrict__ ccb,
    const float* __restrict__ pre_w, const float* __restrict__ pre_b,
    const float* __restrict__ mean_w, const float* __restrict__ mean_b,
    const float* __restrict__ std_w, const float* __restrict__ std_b,
    float* __restrict__ out)
{
    extern __shared__ float sm[];
    float* xwin  = sm + SM_XWIN;
    float* condv = sm + SM_COND;
    float* cproj = sm + SM_CPROJ;
    float* wbuf  = sm + SM_WBUF;
    float* bufA  = sm + SM_BUFA;
    float* bufB  = sm + SM_BUFB;
    float* wfull = bufA + 8192;     // 24576 floats free once activations are small (l>=3)

    const int n   = blockIdx.x;
    const int tid = threadIdx.x;

    // load input window + conditioning vector
    for (int i = tid; i < RF; i += 512) xwin[i] = g_prevx[n + i];
    if (tid < MGC) condv[tid] = g_cond[n * MGC + tid];
    __syncthreads();

    // per-layer conditioning projections: cproj[l*128 + k*64 + o]
    for (int idx = tid; idx < NL * 2 * FS; idx += 512) {
        int l = idx >> 7;
        int k = (idx >> 6) & 1;
        int o = idx & 63;
        int base = ((s * NL + l) * 2 + k) * FS + o;
        const float* wr = ccw + (size_t)base * MGC;
        float acc = ccb[base];
#pragma unroll
        for (int m = 0; m < MGC; m++) acc += condv[m] * wr[m];
        cproj[idx] = acc;
    }
    // layer-0 weights (3*64*1*2 = 384 floats)
    for (int i = tid; i < 384; i += 512) wbuf[i] = conv0_w[s * 384 + i];
    __syncthreads();

    // ---- layer 0: C=1, L 1024 -> 512 ----
    {
        const float* b = conv_b + (size_t)(s * NL + 0) * 3 * FS;
        for (int idx = tid; idx < FS * 512; idx += 512) {
            int o = idx >> 9, j = idx & 511;
            float x0 = xwin[2 * j], x1 = xwin[2 * j + 1];
            float iv = wbuf[o * 2]       * x0 + wbuf[o * 2 + 1]       * x1 + b[o]        + cproj[o];
            float gv = wbuf[128 + o * 2] * x0 + wbuf[128 + o * 2 + 1] * x1 + b[64 + o]   + cproj[64 + o];
            float rv = wbuf[256 + o * 2] * x0 + wbuf[256 + o * 2 + 1] * x1 + b[128 + o];
            bufA[o * 512 + j] = (tanhf(iv) * sigmoidf_(gv) + rv) * VSCALE;
        }
    }

    // ---- layers 1..9: C=64, strided conv k=2 s=2 ----
    // Work item = (o, jq): 3 convs x 4 consecutive outputs, K=128 reduction.
    for (int l = 1; l < NL; l++) {
        const int Lin  = RF >> l;
        const int Lout = Lin >> 1;
        float* src = (l & 1) ? bufA : bufB;
        float* dst = (l & 1) ? bufB : bufA;
        const float* Wg = convs_w + (size_t)(s * 9 + (l - 1)) * 3 * FS * FS * 2;
        const float* b  = conv_b + (size_t)(s * NL + l) * 3 * FS;
        const float bI0 = 0.f; (void)bI0;

        if (l == NL - 1) {
            // ---- Lout = 1, Lin = 2: scalar path (float2 rows) ----
            __syncthreads();
            for (int i = tid; i < 6144; i += 512)
                ((float4*)wfull)[i] = ((const float4*)Wg)[i];
            __syncthreads();
            if (tid < FS) {
                const int o = tid;
                const float2* w2 = (const float2*)wfull;
                const float2* sr = (const float2*)src;
                float a0 = 0.f, a1 = 0.f, a2 = 0.f;
#pragma unroll 8
                for (int c = 0; c < FS; c++) {
                    float2 xv = sr[c];
                    float2 w0 = w2[(0 * FS + o) * FS + c];
                    float2 w1 = w2[(1 * FS + o) * FS + c];
                    float2 w3 = w2[(2 * FS + o) * FS + c];
                    a0 = fmaf(w0.x, xv.x, a0); a0 = fmaf(w0.y, xv.y, a0);
                    a1 = fmaf(w1.x, xv.x, a1); a1 = fmaf(w1.y, xv.y, a1);
                    a2 = fmaf(w3.x, xv.x, a2); a2 = fmaf(w3.y, xv.y, a2);
                }
                float bI = b[o] + cproj[l * 128 + o];
                float bG = b[64 + o] + cproj[l * 128 + 64 + o];
                float bR = b[128 + o];
                dst[o] = (tanhf(a0 + bI) * sigmoidf_(a1 + bG) + a2 + bR) * VSCALE;
            }
            __syncthreads();
            continue;
        }

        const int lq_sh = (l <= 7) ? (7 - l) : 0;    // log2(items-per-o)
        const int Lq    = 1 << lq_sh;                // j-quads per o (>=1)

        if (Lout >= 128) {
            // l = 1,2 : weights too big + activations too big -> 16-o blocks
            for (int ob = 0; ob < FS; ob += 16) {
                __syncthreads();
                for (int i = tid; i < 1536; i += 512) {
                    int kk = i >> 9, rest = i & 511;
                    ((float4*)wbuf)[i] = ((const float4*)(Wg + kk * (FS * 128) + ob * 128))[rest];
                }
                __syncthreads();
                const float2* w2 = (const float2*)wbuf;
                const int nit = 16 << lq_sh;
                for (int item = tid; item < nit; item += 512) {
                    const int ol = item >> lq_sh;
                    const int jq = item & (Lq - 1);
                    const int o  = ob + ol;
                    float acc[12];
#pragma unroll
                    for (int a = 0; a < 12; a++) acc[a] = 0.f;
#pragma unroll 4
                    for (int c = 0; c < FS; c++) {
                        const float4* sr = (const float4*)(src + c * Lin);
                        float4 xa = sr[2 * jq];
                        float4 xb = sr[2 * jq + 1];
#pragma unroll
                        for (int k = 0; k < 3; k++) {
                            float2 wv = w2[(k * 16 + ol) * FS + c];
                            acc[k*4+0] = fmaf(wv.x, xa.x, acc[k*4+0]); acc[k*4+0] = fmaf(wv.y, xa.y, acc[k*4+0]);
                            acc[k*4+1] = fmaf(wv.x, xa.z, acc[k*4+1]); acc[k*4+1] = fmaf(wv.y, xa.w, acc[k*4+1]);
                            acc[k*4+2] = fmaf(wv.x, xb.x, acc[k*4+2]); acc[k*4+2] = fmaf(wv.y, xb.y, acc[k*4+2]);
                            acc[k*4+3] = fmaf(wv.x, xb.z, acc[k*4+3]); acc[k*4+3] = fmaf(wv.y, xb.w, acc[k*4+3]);
                        }
                    }
                    float bI = b[o] + cproj[l * 128 + o];
                    float bG = b[64 + o] + cproj[l * 128 + 64 + o];
                    float bR = b[128 + o];
#pragma unroll
                    for (int jj = 0; jj < 4; jj++) {
                        int j = 4 * jq + jj;
                        dst[o * Lout + j] =
                            (tanhf(acc[jj] + bI) * sigmoidf_(acc[4 + jj] + bG)
                             + acc[8 + jj] + bR) * VSCALE;
                    }
                }
            }
            __syncthreads();
        } else {
            // l = 3..8 : full-layer weights fit in bufA tail (activations shrank)
            __syncthreads();
            for (int i = tid; i < 6144; i += 512)
                ((float4*)wfull)[i] = ((const float4*)Wg)[i];
            __syncthreads();
            const float2* w2 = (const float2*)wfull;
            const int nit = FS << lq_sh;
            for (int item = tid; item < nit; item += 512) {
                const int o  = item >> lq_sh;
                const int jq = item & (Lq - 1);
                float acc[12];
#pragma unroll
                for (int a = 0; a < 12; a++) acc[a] = 0.f;
#pragma unroll 4
                for (int c = 0; c < FS; c++) {
                    const float4* sr = (const float4*)(src + c * Lin);
                    float4 xa = sr[2 * jq];
                    float4 xb = sr[2 * jq + 1];   // may read past row for tiny Lin; in-buffer, discarded
#pragma unroll
                    for (int k = 0; k < 3; k++) {
                        float2 wv = w2[(k * FS + o) * FS + c];
                        acc[k*4+0] = fmaf(wv.x, xa.x, acc[k*4+0]); acc[k*4+0] = fmaf(wv.y, xa.y, acc[k*4+0]);
                        acc[k*4+1] = fmaf(wv.x, xa.z, acc[k*4+1]); acc[k*4+1] = fmaf(wv.y, xa.w, acc[k*4+1]);
                        acc[k*4+2] = fmaf(wv.x, xb.x, acc[k*4+2]); acc[k*4+2] = fmaf(wv.y, xb.y, acc[k*4+2]);
                        acc[k*4+3] = fmaf(wv.x, xb.z, acc[k*4+3]); acc[k*4+3] = fmaf(wv.y, xb.w, acc[k*4+3]);
                    }
                }
                float bI = b[o] + cproj[l * 128 + o];
                float bG = b[64 + o] + cproj[l * 128 + 64 + o];
                float bR = b[128 + o];
#pragma unroll
                for (int jj = 0; jj < 4; jj++) {
                    int j = 4 * jq + jj;
                    if (j < Lout)
                        dst[o * Lout + j] =
                            (tanhf(acc[jj] + bI) * sigmoidf_(acc[4 + jj] + bG)
                             + acc[8 + jj] + bR) * VSCALE;
                }
            }
            __syncthreads();
        }
    }

    // ---- head: x (64) -> pre (256) -> mean/logvar ----
    __syncthreads();
    {
        float mpart = 0.f, vpart = 0.f;
        if (tid < 256) {
            const int p = tid;
            const float* pw = pre_w + (size_t)(s * 256 + p) * FS;
            float acc = pre_b[s * 256 + p];
#pragma unroll
            for (int o = 0; o < FS; o++) acc += bufB[o] * pw[o];
            float pre = fmaxf(acc, 0.f);
            mpart = pre * mean_w[s * 256 + p];
            vpart = pre * std_w[s * 256 + p];
        }
        float* red  = wbuf;
        float* red2 = wbuf + 256;
        __syncthreads();
        if (tid < 256) { red[tid] = mpart; red2[tid] = vpart; }
        __syncthreads();
        for (int st = 128; st > 0; st >>= 1) {
            if (tid < st) { red[tid] += red[tid + st]; red2[tid] += red2[tid + st]; }
            __syncthreads();
        }
        if (tid == 0) {
            float mean   = red[0]  + mean_b[s];
            float logvar = red2[0] + std_b[s];
            float eps = g_prevx[RF + n];
            float nv = eps * expf(0.5f * logvar) + mean;
            g_new[n] = nv;
            if (s == NS - 1) {
                out[n] = nv;
                out[NWIN + n] = mean;
                out[2 * NWIN + n] = logvar;
            }
        }
    }
}

// chain: prev_x[RF:] = new ; tails[s] = new[-RF:]
__global__ void k_update(int s, float* __restrict__ out) {
    int i = blockIdx.x * blockDim.x + threadIdx.x;
    if (i < NWIN) {
        float v = g_new[i];
        g_prevx[RF + i] = v;
        if (i >= NWIN - RF) out[3 * NWIN + s * RF + (i - (NWIN - RF))] = v;
    }
}

// ---------------- launcher ----------------
extern "C" void kernel_launch(void* const* d_in, const int* in_sizes, int n_in,
                              void* d_out, int out_size) {
    const float* mgc     = (const float*)d_in[0];
    const float* noise   = (const float*)d_in[1];
    const float* cond_w  = (const float*)d_in[2];
    const float* cond_b  = (const float*)d_in[3];
    const float* conv0_w = (const float*)d_in[4];
    const float* convs_w = (const float*)d_in[5];
    const float* conv_b  = (const float*)d_in[6];
    const float* ccw     = (const float*)d_in[7];
    const float* ccb     = (const float*)d_in[8];
    const float* pre_w   = (const float*)d_in[9];
    const float* pre_b   = (const float*)d_in[10];
    const float* mean_w  = (const float*)d_in[11];
    const float* mean_b  = (const float*)d_in[12];
    const float* std_w   = (const float*)d_in[13];
    const float* std_b   = (const float*)d_in[14];
    float* out = (float*)d_out;

    cudaFuncSetAttribute(k_stage, cudaFuncAttributeMaxDynamicSharedMemorySize, SMEM_BYTES);

    k_copy<<<(RF + NWIN + 255) / 256, 256>>>(noise);
    k_cond<<<NWIN, 64>>>(mgc, cond_w, cond_b);

    for (int s = 0; s < NS; s++) {
        k_stage<<<NWIN, 512, SMEM_BYTES>>>(s, conv0_w, convs_w, conv_b,
                                           ccw, ccb, pre_w, pre_b,
                                           mean_w, mean_b, std_w, std_b, out);
        k_update<<<(NWIN + 255) / 256, 256>>>(s, out);
    }
}

// round 6
// speedup vs baseline: 1.5807x; 1.5807x over previous
#include <cuda_runtime.h>
#include <math.h>

#define RF   1024
#define US   200
#define MGC  60
#define FS   64
#define NS   4
#define NL   10
#define NWIN 1600
#define VSCALE 0.70710678118f

// Scratch (device globals: no allocation allowed)
__device__ float g_prevx[RF + NWIN];
__device__ float g_new[NWIN];
__device__ float g_cond[NWIN * MGC];

// ---------------- prep kernels ----------------
__global__ void k_copy(const float* __restrict__ noise) {
    int i = blockIdx.x * blockDim.x + threadIdx.x;
    if (i < RF + NWIN) g_prevx[i] = noise[i];
}

__global__ void k_cond(const float* __restrict__ mgc,
                       const float* __restrict__ cond_w,
                       const float* __restrict__ cond_b) {
    int n = blockIdx.x;
    int m = threadIdx.x;
    if (m >= MGC) return;
    int f = n / US, u = n % US;
    int r = u * MGC + m;
    const float* wrow = cond_w + (size_t)r * MGC;
    const float* mrow = mgc + f * MGC;
    float acc = cond_b[r];
#pragma unroll
    for (int k = 0; k < MGC; k++) acc += mrow[k] * wrow[k];
    g_cond[n * MGC + m] = tanhf(acc);
}

// ---------------- per-stage kernel: one CTA = one window ----------------
// smem layout (floats):
//   xwin  [1024]
//   condv [64]
//   cproj [NL*2*64 = 1280]
//   wbuf  [3*16*128 = 6144]   (l=1,2 weight blocks, layer0 weights, reduction)
//   bufA  [64*512 = 32768]    (tail bufA+8192.. doubles as full-layer weights for l>=3)
//   bufB  [64*256 = 16384]
#define SM_XWIN  0
#define SM_COND  1024
#define SM_CPROJ 1088
#define SM_WBUF  2368
#define SM_BUFA  8512
#define SM_BUFB  41280
#define SM_FLOATS (41280 + 16384)
#define SMEM_BYTES (SM_FLOATS * 4)

__device__ __forceinline__ float sigmoidf_(float v) {
    return 1.0f / (1.0f + expf(-v));
}

__global__ __launch_bounds__(512, 1) void k_stage(
    int s,
    const float* __restrict__ conv0_w, const float* __restrict__ convs_w,
    const float* __restrict__ conv_b,
    const float* __restrict__ ccw, const float* __restrict__ ccb,
    const float* __restrict__ pre_w, const float* __restrict__ pre_b,
    const float* __restrict__ mean_w, const float* __restrict__ mean_b,
    const float* __restrict__ std_w, const float* __restrict__ std_b,
    float* __restrict__ out)
{
    extern __shared__ float sm[];
    float* xwin  = sm + SM_XWIN;
    float* condv = sm + SM_COND;
    float* cproj = sm + SM_CPROJ;
    float* wbuf  = sm + SM_WBUF;
    float* bufA  = sm + SM_BUFA;
    float* bufB  = sm + SM_BUFB;
    float* wfull = bufA + 8192;     // 24576 floats free once activations are small (l>=3)

    const int n   = blockIdx.x;
    const int tid = threadIdx.x;

    // load input window + conditioning vector
    for (int i = tid; i < RF; i += 512) xwin[i] = g_prevx[n + i];
    if (tid < MGC) condv[tid] = g_cond[n * MGC + tid];
    __syncthreads();

    // per-layer conditioning projections: cproj[l*128 + k*64 + o]
    for (int idx = tid; idx < NL * 2 * FS; idx += 512) {
        int l = idx >> 7;
        int k = (idx >> 6) & 1;
        int o = idx & 63;
        int base = ((s * NL + l) * 2 + k) * FS + o;
        const float* wr = ccw + (size_t)base * MGC;
        float acc = ccb[base];
#pragma unroll
        for (int m = 0; m < MGC; m++) acc += condv[m] * wr[m];
        cproj[idx] = acc;
    }
    // layer-0 weights (3*64*1*2 = 384 floats)
    for (int i = tid; i < 384; i += 512) wbuf[i] = conv0_w[s * 384 + i];
    __syncthreads();

    // ---- layer 0: C=1, L 1024 -> 512 ----
    {
        const float* b = conv_b + (size_t)(s * NL + 0) * 3 * FS;
        for (int idx = tid; idx < FS * 512; idx += 512) {
            int o = idx >> 9, j = idx & 511;
            float x0 = xwin[2 * j], x1 = xwin[2 * j + 1];
            float iv = wbuf[o * 2]       * x0 + wbuf[o * 2 + 1]       * x1 + b[o]        + cproj[o];
            float gv = wbuf[128 + o * 2] * x0 + wbuf[128 + o * 2 + 1] * x1 + b[64 + o]   + cproj[64 + o];
            float rv = wbuf[256 + o * 2] * x0 + wbuf[256 + o * 2 + 1] * x1 + b[128 + o];
            bufA[o * 512 + j] = (tanhf(iv) * sigmoidf_(gv) + rv) * VSCALE;
        }
    }

    // ---- layers 1..9: C=64, strided conv k=2 s=2 ----
    // Work item = (o, jq): 3 convs x 4 consecutive outputs, K=128 reduction.
    for (int l = 1; l < NL; l++) {
        const int Lin  = RF >> l;
        const int Lout = Lin >> 1;
        float* src = (l & 1) ? bufA : bufB;
        float* dst = (l & 1) ? bufB : bufA;
        const float* Wg = convs_w + (size_t)(s * 9 + (l - 1)) * 3 * FS * FS * 2;
        const float* b  = conv_b + (size_t)(s * NL + l) * 3 * FS;
        const float bI0 = 0.f; (void)bI0;

        if (l == NL - 1) {
            // ---- Lout = 1, Lin = 2: scalar path (float2 rows) ----
            __syncthreads();
            for (int i = tid; i < 6144; i += 512)
                ((float4*)wfull)[i] = ((const float4*)Wg)[i];
            __syncthreads();
            if (tid < FS) {
                const int o = tid;
                const float2* w2 = (const float2*)wfull;
                const float2* sr = (const float2*)src;
                float a0 = 0.f, a1 = 0.f, a2 = 0.f;
#pragma unroll 8
                for (int c = 0; c < FS; c++) {
                    float2 xv = sr[c];
                    float2 w0 = w2[(0 * FS + o) * FS + c];
                    float2 w1 = w2[(1 * FS + o) * FS + c];
                    float2 w3 = w2[(2 * FS + o) * FS + c];
                    a0 = fmaf(w0.x, xv.x, a0); a0 = fmaf(w0.y, xv.y, a0);
                    a1 = fmaf(w1.x, xv.x, a1); a1 = fmaf(w1.y, xv.y, a1);
                    a2 = fmaf(w3.x, xv.x, a2); a2 = fmaf(w3.y, xv.y, a2);
                }
                float bI = b[o] + cproj[l * 128 + o];
                float bG = b[64 + o] + cproj[l * 128 + 64 + o];
                float bR = b[128 + o];
                dst[o] = (tanhf(a0 + bI) * sigmoidf_(a1 + bG) + a2 + bR) * VSCALE;
            }
            __syncthreads();
            continue;
        }

        const int lq_sh = (l <= 7) ? (7 - l) : 0;    // log2(items-per-o)
        const int Lq    = 1 << lq_sh;                // j-quads per o (>=1)

        if (Lout >= 128) {
            // l = 1,2 : weights too big + activations too big -> 16-o blocks
            for (int ob = 0; ob < FS; ob += 16) {
                __syncthreads();
                for (int i = tid; i < 1536; i += 512) {
                    int kk = i >> 9, rest = i & 511;
                    ((float4*)wbuf)[i] = ((const float4*)(Wg + kk * (FS * 128) + ob * 128))[rest];
                }
                __syncthreads();
                const float2* w2 = (const float2*)wbuf;
                const int nit = 16 << lq_sh;
                for (int item = tid; item < nit; item += 512) {
                    const int ol = item >> lq_sh;
                    const int jq = item & (Lq - 1);
                    const int o  = ob + ol;
                    float acc[12];
#pragma unroll
                    for (int a = 0; a < 12; a++) acc[a] = 0.f;
#pragma unroll 4
                    for (int c = 0; c < FS; c++) {
                        const float4* sr = (const float4*)(src + c * Lin);
                        float4 xa = sr[2 * jq];
                        float4 xb = sr[2 * jq + 1];
#pragma unroll
                        for (int k = 0; k < 3; k++) {
                            float2 wv = w2[(k * 16 + ol) * FS + c];
                            acc[k*4+0] = fmaf(wv.x, xa.x, acc[k*4+0]); acc[k*4+0] = fmaf(wv.y, xa.y, acc[k*4+0]);
                            acc[k*4+1] = fmaf(wv.x, xa.z, acc[k*4+1]); acc[k*4+1] = fmaf(wv.y, xa.w, acc[k*4+1]);
                            acc[k*4+2] = fmaf(wv.x, xb.x, acc[k*4+2]); acc[k*4+2] = fmaf(wv.y, xb.y, acc[k*4+2]);
                            acc[k*4+3] = fmaf(wv.x, xb.z, acc[k*4+3]); acc[k*4+3] = fmaf(wv.y, xb.w, acc[k*4+3]);
                        }
                    }
                    float bI = b[o] + cproj[l * 128 + o];
                    float bG = b[64 + o] + cproj[l * 128 + 64 + o];
                    float bR = b[128 + o];
#pragma unroll
                    for (int jj = 0; jj < 4; jj++) {
                        int j = 4 * jq + jj;
                        dst[o * Lout + j] =
                            (tanhf(acc[jj] + bI) * sigmoidf_(acc[4 + jj] + bG)
                             + acc[8 + jj] + bR) * VSCALE;
                    }
                }
            }
            __syncthreads();
        } else {
            // l = 3..8 : full-layer weights fit in bufA tail (activations shrank)
            __syncthreads();
            for (int i = tid; i < 6144; i += 512)
                ((float4*)wfull)[i] = ((const float4*)Wg)[i];
            __syncthreads();
            const float2* w2 = (const float2*)wfull;
            const int nit = FS << lq_sh;
            for (int item = tid; item < nit; item += 512) {
                const int o  = item >> lq_sh;
                const int jq = item & (Lq - 1);
                float acc[12];
#pragma unroll
                for (int a = 0; a < 12; a++) acc[a] = 0.f;
#pragma unroll 4
                for (int c = 0; c < FS; c++) {
                    const float4* sr = (const float4*)(src + c * Lin);
                    float4 xa = sr[2 * jq];
                    float4 xb = sr[2 * jq + 1];   // may read past row for tiny Lin; in-buffer, discarded
#pragma unroll
                    for (int k = 0; k < 3; k++) {
                        float2 wv = w2[(k * FS + o) * FS + c];
                        acc[k*4+0] = fmaf(wv.x, xa.x, acc[k*4+0]); acc[k*4+0] = fmaf(wv.y, xa.y, acc[k*4+0]);
                        acc[k*4+1] = fmaf(wv.x, xa.z, acc[k*4+1]); acc[k*4+1] = fmaf(wv.y, xa.w, acc[k*4+1]);
                        acc[k*4+2] = fmaf(wv.x, xb.x, acc[k*4+2]); acc[k*4+2] = fmaf(wv.y, xb.y, acc[k*4+2]);
                        acc[k*4+3] = fmaf(wv.x, xb.z, acc[k*4+3]); acc[k*4+3] = fmaf(wv.y, xb.w, acc[k*4+3]);
                    }
                }
                float bI = b[o] + cproj[l * 128 + o];
                float bG = b[64 + o] + cproj[l * 128 + 64 + o];
                float bR = b[128 + o];
#pragma unroll
                for (int jj = 0; jj < 4; jj++) {
                    int j = 4 * jq + jj;
                    if (j < Lout)
                        dst[o * Lout + j] =
                            (tanhf(acc[jj] + bI) * sigmoidf_(acc[4 + jj] + bG)
                             + acc[8 + jj] + bR) * VSCALE;
                }
            }
            __syncthreads();
        }
    }

    // ---- head: x (64) -> pre (256) -> mean/logvar ----
    __syncthreads();
    {
        float mpart = 0.f, vpart = 0.f;
        if (tid < 256) {
            const int p = tid;
            const float* pw = pre_w + (size_t)(s * 256 + p) * FS;
            float acc = pre_b[s * 256 + p];
#pragma unroll
            for (int o = 0; o < FS; o++) acc += bufB[o] * pw[o];
            float pre = fmaxf(acc, 0.f);
            mpart = pre * mean_w[s * 256 + p];
            vpart = pre * std_w[s * 256 + p];
        }
        float* red  = wbuf;
        float* red2 = wbuf + 256;
        __syncthreads();
        if (tid < 256) { red[tid] = mpart; red2[tid] = vpart; }
        __syncthreads();
        for (int st = 128; st > 0; st >>= 1) {
            if (tid < st) { red[tid] += red[tid + st]; red2[tid] += red2[tid + st]; }
            __syncthreads();
        }
        if (tid == 0) {
            float mean   = red[0]  + mean_b[s];
            float logvar = red2[0] + std_b[s];
            float eps = g_prevx[RF + n];
            float nv = eps * expf(0.5f * logvar) + mean;
            g_new[n] = nv;
            if (s == NS - 1) {
                out[n] = nv;
                out[NWIN + n] = mean;
                out[2 * NWIN + n] = logvar;
            }
        }
    }
}

// chain: prev_x[RF:] = new ; tails[s] = new[-RF:]
__global__ void k_update(int s, float* __restrict__ out) {
    int i = blockIdx.x * blockDim.x + threadIdx.x;
    if (i < NWIN) {
        float v = g_new[i];
        g_prevx[RF + i] = v;
        if (i >= NWIN - RF) out[3 * NWIN + s * RF + (i - (NWIN - RF))] = v;
    }
}

// ---------------- launcher ----------------
extern "C" void kernel_launch(void* const* d_in, const int* in_sizes, int n_in,
                              void* d_out, int out_size) {
    const float* mgc     = (const float*)d_in[0];
    const float* noise   = (const float*)d_in[1];
    const float* cond_w  = (const float*)d_in[2];
    const float* cond_b  = (const float*)d_in[3];
    const float* conv0_w = (const float*)d_in[4];
    const float* convs_w = (const float*)d_in[5];
    const float* conv_b  = (const float*)d_in[6];
    const float* ccw     = (const float*)d_in[7];
    const float* ccb     = (const float*)d_in[8];
    const float* pre_w   = (const float*)d_in[9];
    const float* pre_b   = (const float*)d_in[10];
    const float* mean_w  = (const float*)d_in[11];
    const float* mean_b  = (const float*)d_in[12];
    const float* std_w   = (const float*)d_in[13];
    const float* std_b   = (const float*)d_in[14];
    float* out = (float*)d_out;

    cudaFuncSetAttribute(k_stage, cudaFuncAttributeMaxDynamicSharedMemorySize, SMEM_BYTES);

    k_copy<<<(RF + NWIN + 255) / 256, 256>>>(noise);
    k_cond<<<NWIN, 64>>>(mgc, cond_w, cond_b);

    for (int s = 0; s < NS; s++) {
        k_stage<<<NWIN, 512, SMEM_BYTES>>>(s, conv0_w, convs_w, conv_b,
                                           ccw, ccb, pre_w, pre_b,
                                           mean_w, mean_b, std_w, std_b, out);
        k_update<<<(NWIN + 255) / 256, 256>>>(s, out);
    }
}

// round 8
// speedup vs baseline: 2.0761x; 1.3134x over previous
#include <cuda_runtime.h>
#include <math.h>

#define RF   1024
#define US   200
#define MGC  60
#define FS   64
#define NS   4
#define NL   10
#define NWIN 1600
#define VSCALE 0.70710678118f

// Scratch (device globals: no allocation allowed)
__device__ float g_newA[NWIN];
__device__ float g_newB[NWIN];
__device__ float g_cond[NWIN * MGC];
__device__ float g_prep[RF];

// ---------------- prep kernels ----------------
// (also serves as a launch-count shim so ncu -s 5 lands on the last k_stage)
__global__ void k_copy(const float* __restrict__ noise) {
    int i = blockIdx.x * blockDim.x + threadIdx.x;
    if (i < RF) g_prep[i] = noise[i];
}

__global__ void k_cond(const float* __restrict__ mgc,
                       const float* __restrict__ cond_w,
                       const float* __restrict__ cond_b) {
    int n = blockIdx.x;
    int m = threadIdx.x;
    if (m >= MGC) return;
    int f = n / US, u = n % US;
    int r = u * MGC + m;
    const float* wrow = cond_w + (size_t)r * MGC;
    const float* mrow = mgc + f * MGC;
    float acc = cond_b[r];
#pragma unroll
    for (int k = 0; k < MGC; k++) acc += mrow[k] * wrow[k];
    g_cond[n * MGC + m] = tanhf(acc);
}

// ---------------- per-stage kernel: one CTA = one window ----------------
#define SM_XWIN  0
#define SM_COND  1024
#define SM_CPROJ 1088
#define SM_WBUF  2368
#define SM_BUFA  8512
#define SM_BUFB  41280
#define SM_FLOATS (41280 + 16384)
#define SMEM_BYTES (SM_FLOATS * 4)

__device__ __forceinline__ float sigmoidf_(float v) {
    return 1.0f / (1.0f + expf(-v));
}

__device__ __forceinline__ float gatef_(float aI, float aG, float aR) {
    return (tanhf(aI) * sigmoidf_(aG) + aR) * VSCALE;
}

__global__ __launch_bounds__(512, 1) void k_stage(
    int s,
    const float* __restrict__ noise,
    const float* __restrict__ gin,    // g_new of previous stage (unused for s==0)
    float* __restrict__ gout,         // g_new of this stage
    const float* __restrict__ conv0_w, const float* __restrict__ convs_w,
    const float* __restrict__ conv_b,
    const float* __restrict__ pre_w, const float* __restrict__ pre_b,
    const float* __restrict__ mean_w, const float* __restrict__ mean_b,
    const float* __restrict__ std_w, const float* __restrict__ std_b,
    const float* __restrict__ ccw, const float* __restrict__ ccb,
    float* __restrict__ out)
{
    extern __shared__ float sm[];
    float* xwin  = sm + SM_XWIN;
    float* condv = sm + SM_COND;
    float* cproj = sm + SM_CPROJ;
    float* wbuf  = sm + SM_WBUF;
    float* bufA  = sm + SM_BUFA;
    float* bufB  = sm + SM_BUFB;
    float* wfull = bufA + 8192;     // 24576 floats: free for l>=3

    const int n   = blockIdx.x;
    const int tid = threadIdx.x;

    // input window: prev_x[n .. n+RF) ; prev_x = noise (s==0) else [noise[:RF], gin]
    for (int i = tid; i < RF; i += 512) {
        int idx = n + i;
        float v;
        if (s == 0 || idx < RF) v = noise[idx];
        else                    v = gin[idx - RF];
        xwin[i] = v;
    }
    if (tid < MGC) condv[tid] = g_cond[n * MGC + tid];
    __syncthreads();

    // per-layer conditioning projections: cproj[l*128 + k*64 + o]
    for (int idx = tid; idx < NL * 2 * FS; idx += 512) {
        int l = idx >> 7;
        int k = (idx >> 6) & 1;
        int o = idx & 63;
        int base = ((s * NL + l) * 2 + k) * FS + o;
        const float* wr = ccw + (size_t)base * MGC;
        float acc = ccb[base];
#pragma unroll
        for (int m = 0; m < MGC; m++) acc += condv[m] * wr[m];
        cproj[idx] = acc;
    }
    // layer-0 weights (384 floats)
    for (int i = tid; i < 384; i += 512) wbuf[i] = conv0_w[s * 384 + i];
    __syncthreads();

    // ---- layer 0: C=1, L 1024 -> 512 ----
    {
        const float* b = conv_b + (size_t)(s * NL + 0) * 3 * FS;
        for (int idx = tid; idx < FS * 512; idx += 512) {
            int o = idx >> 9, j = idx & 511;
            float x0 = xwin[2 * j], x1 = xwin[2 * j + 1];
            float iv = wbuf[o * 2]       * x0 + wbuf[o * 2 + 1]       * x1 + b[o]      + cproj[o];
            float gv = wbuf[128 + o * 2] * x0 + wbuf[128 + o * 2 + 1] * x1 + b[64 + o] + cproj[64 + o];
            float rv = wbuf[256 + o * 2] * x0 + wbuf[256 + o * 2 + 1] * x1 + b[128 + o];
            bufA[o * 512 + j] = gatef_(iv, gv, rv);
        }
    }

    // ---- layers 1,2: 16-o weight blocks in wbuf ----
    for (int l = 1; l <= 2; l++) {
        const int Lin  = RF >> l;          // 512, 256
        const int Lout = Lin >> 1;         // 256, 128
        const int To   = Lout >> 2;        // 64, 32
        const int toSh = (l == 1) ? 6 : 5;
        float* src = (l & 1) ? bufA : bufB;
        float* dst = (l & 1) ? bufB : bufA;
        const float* Wg = convs_w + (size_t)(s * 9 + (l - 1)) * 3 * FS * FS * 2;
        const float* b  = conv_b + (size_t)(s * NL + l) * 3 * FS;
        const int rs4 = Lin >> 2;

        for (int ob = 0; ob < FS; ob += 16) {
            __syncthreads();
            for (int i = tid; i < 1536; i += 512) {
                int kk = i >> 9, rest = i & 511;
                ((float4*)wbuf)[i] = ((const float4*)(Wg + kk * (FS * 128) + ob * 128))[rest];
            }
            __syncthreads();
            const float2* w2 = (const float2*)wbuf;   // [k][ol][c]
            const int nit = 16 << toSh;
            for (int item = tid; item < nit; item += 512) {
                const int ol = item >> toSh;
                const int q  = item & (To - 1);
                const int o  = ob + ol;
                float acc[12];
#pragma unroll
                for (int a = 0; a < 12; a++) acc[a] = 0.f;
                const float4* r0 = (const float4*)src;
#pragma unroll 4
                for (int c = 0; c < FS; c++) {
                    const float4* r = r0 + c * rs4;
                    float4 xa = r[q];
                    float4 xb = r[q + To];
#pragma unroll
                    for (int k = 0; k < 3; k++) {
                        float2 wv = w2[((k * 16 + ol) << 6) + c];
                        acc[k*4+0] = fmaf(wv.x, xa.x, acc[k*4+0]); acc[k*4+0] = fmaf(wv.y, xa.y, acc[k*4+0]);
                        acc[k*4+1] = fmaf(wv.x, xa.z, acc[k*4+1]); acc[k*4+1] = fmaf(wv.y, xa.w, acc[k*4+1]);
                        acc[k*4+2] = fmaf(wv.x, xb.x, acc[k*4+2]); acc[k*4+2] = fmaf(wv.y, xb.y, acc[k*4+2]);
                        acc[k*4+3] = fmaf(wv.x, xb.z, acc[k*4+3]); acc[k*4+3] = fmaf(wv.y, xb.w, acc[k*4+3]);
                    }
                }
                float bI = b[o] + cproj[l * 128 + o];
                float bG = b[64 + o] + cproj[l * 128 + 64 + o];
                float bR = b[128 + o];
                float2* drow = (float2*)(dst + o * Lout);
                drow[q]      = make_float2(gatef_(acc[0] + bI, acc[4] + bG, acc[8]  + bR),
                                           gatef_(acc[1] + bI, acc[5] + bG, acc[9]  + bR));
                drow[q + To] = make_float2(gatef_(acc[2] + bI, acc[6] + bG, acc[10] + bR),
                                           gatef_(acc[3] + bI, acc[7] + bG, acc[11] + bR));
            }
        }
        __syncthreads();
    }

    // ---- layers 3..7: full-layer weights in wfull, XOR-swizzled [k][o][c^o] ----
    for (int l = 3; l <= 7; l++) {
        const int Lin  = RF >> l;          // 128..8
        const int Lout = Lin >> 1;         // 64..4
        const int toSh = 7 - l;            // log2(To): 4..0
        const int To   = 1 << toSh;
        float* src = (l & 1) ? bufA : bufB;
        float* dst = (l & 1) ? bufB : bufA;
        const float* Wg = convs_w + (size_t)(s * 9 + (l - 1)) * 3 * FS * FS * 2;
        const float* b  = conv_b + (size_t)(s * NL + l) * 3 * FS;
        const int rs4 = Lin >> 2;

        __syncthreads();
        {
            const float2* src2 = (const float2*)Wg;
            float2* w2 = (float2*)wfull;
            for (int g = tid; g < 12288; g += 512) {
                int o = (g >> 6) & 63;
                int didx = (g & ~63) | ((g ^ o) & 63);
                w2[didx] = src2[g];
            }
        }
        __syncthreads();
        const float2* w2 = (const float2*)wfull;
        const int nit = FS << toSh;
        for (int item = tid; item < nit; item += 512) {
            const int o = item >> toSh;
            const int q = item & (To - 1);
            float acc[12];
#pragma unroll
            for (int a = 0; a < 12; a++) acc[a] = 0.f;
            const float4* r0 = (const float4*)src;
#pragma unroll 4
            for (int c = 0; c < FS; c++) {
                const float4* r = r0 + c * rs4;
                float4 xa = r[q];
                float4 xb = r[q + To];
                int cx = c ^ o;
#pragma unroll
                for (int k = 0; k < 3; k++) {
                    float2 wv = w2[(((k << 6) + o) << 6) + cx];
                    acc[k*4+0] = fmaf(wv.x, xa.x, acc[k*4+0]); acc[k*4+0] = fmaf(wv.y, xa.y, acc[k*4+0]);
                    acc[k*4+1] = fmaf(wv.x, xa.z, acc[k*4+1]); acc[k*4+1] = fmaf(wv.y, xa.w, acc[k*4+1]);
                    acc[k*4+2] = fmaf(wv.x, xb.x, acc[k*4+2]); acc[k*4+2] = fmaf(wv.y, xb.y, acc[k*4+2]);
                    acc[k*4+3] = fmaf(wv.x, xb.z, acc[k*4+3]); acc[k*4+3] = fmaf(wv.y, xb.w, acc[k*4+3]);
                }
            }
            float bI = b[o] + cproj[l * 128 + o];
            float bG = b[64 + o] + cproj[l * 128 + 64 + o];
            float bR = b[128 + o];
            float2* drow = (float2*)(dst + o * Lout);
            drow[q]      = make_float2(gatef_(acc[0] + bI, acc[4] + bG, acc[8]  + bR),
                                       gatef_(acc[1] + bI, acc[5] + bG, acc[9]  + bR));
            drow[q + To] = make_float2(gatef_(acc[2] + bI, acc[6] + bG, acc[10] + bR),
                                       gatef_(acc[3] + bI, acc[7] + bG, acc[11] + bR));
        }
        __syncthreads();
    }

    // ---- layer 8: Lin=4, Lout=2 ----
    {
        const int l = 8;
        float* src = bufB;   // l even: src = bufB
        float* dst = bufA;
        const float* Wg = convs_w + (size_t)(s * 9 + (l - 1)) * 3 * FS * FS * 2;
        const float* b  = conv_b + (size_t)(s * NL + l) * 3 * FS;

        __syncthreads();
        {
            const float2* src2 = (const float2*)Wg;
            float2* w2 = (float2*)wfull;
            for (int g = tid; g < 12288; g += 512) {
                int o = (g >> 6) & 63;
                int didx = (g & ~63) | ((g ^ o) & 63);
                w2[didx] = src2[g];
            }
        }
        __syncthreads();
        if (tid < FS) {
            const int o = tid;
            const float2* w2 = (const float2*)wfull;
            float acc[6];
#pragma unroll
            for (int a = 0; a < 6; a++) acc[a] = 0.f;
#pragma unroll 4
            for (int c = 0; c < FS; c++) {
                float4 xa = *(const float4*)(src + (c << 2));
                int cx = c ^ o;
#pragma unroll
                for (int k = 0; k < 3; k++) {
                    float2 wv = w2[(((k << 6) + o) << 6) + cx];
                    acc[k*2+0] = fmaf(wv.x, xa.x, acc[k*2+0]); acc[k*2+0] = fmaf(wv.y, xa.y, acc[k*2+0]);
                    acc[k*2+1] = fmaf(wv.x, xa.z, acc[k*2+1]); acc[k*2+1] = fmaf(wv.y, xa.w, acc[k*2+1]);
                }
            }
            float bI = b[o] + cproj[l * 128 + o];
            float bG = b[64 + o] + cproj[l * 128 + 64 + o];
            float bR = b[128 + o];
            ((float2*)(dst + o * 2))[0] =
                make_float2(gatef_(acc[0] + bI, acc[2] + bG, acc[4] + bR),
                            gatef_(acc[1] + bI, acc[3] + bG, acc[5] + bR));
        }
        __syncthreads();
    }

    // ---- layer 9: Lin=2, Lout=1 ----
    {
        const int l = 9;
        float* src = bufA;
        float* dst = bufB;
        const float* Wg = convs_w + (size_t)(s * 9 + (l - 1)) * 3 * FS * FS * 2;
        const float* b  = conv_b + (size_t)(s * NL + l) * 3 * FS;

        {
            const float2* src2 = (const float2*)Wg;
            float2* w2 = (float2*)wfull;
            for (int g = tid; g < 12288; g += 512) {
                int o = (g >> 6) & 63;
                int didx = (g & ~63) | ((g ^ o) & 63);
                w2[didx] = src2[g];
            }
        }
        __syncthreads();
        if (tid < FS) {
            const int o = tid;
            const float2* w2 = (const float2*)wfull;
            const float2* sr = (const float2*)src;
            float a0 = 0.f, a1 = 0.f, a2 = 0.f;
#pragma unroll 8
            for (int c = 0; c < FS; c++) {
                float2 xv = sr[c];
                int cx = c ^ o;
                float2 w0 = w2[((0 * FS + o) << 6) + cx];
                float2 w1 = w2[((1 * FS + o) << 6) + cx];
                float2 w3 = w2[((2 * FS + o) << 6) + cx];
                a0 = fmaf(w0.x, xv.x, a0); a0 = fmaf(w0.y, xv.y, a0);
                a1 = fmaf(w1.x, xv.x, a1); a1 = fmaf(w1.y, xv.y, a1);
                a2 = fmaf(w3.x, xv.x, a2); a2 = fmaf(w3.y, xv.y, a2);
            }
            float bI = b[o] + cproj[l * 128 + o];
            float bG = b[64 + o] + cproj[l * 128 + 64 + o];
            float bR = b[128 + o];
            dst[o] = gatef_(a0 + bI, a1 + bG, a2 + bR);
        }
        __syncthreads();
    }

    // ---- head: x (64) -> pre (256) -> mean/logvar, fused chain update ----
    {
        float mpart = 0.f, vpart = 0.f;
        if (tid < 256) {
            const int p = tid;
            const float* pw = pre_w + (size_t)(s * 256 + p) * FS;
            float acc = pre_b[s * 256 + p];
#pragma unroll
            for (int o = 0; o < FS; o++) acc += bufB[o] * pw[o];
            float pre = fmaxf(acc, 0.f);
            mpart = pre * mean_w[s * 256 + p];
            vpart = pre * std_w[s * 256 + p];
        }
        float* red  = wbuf;
        float* red2 = wbuf + 256;
        __syncthreads();
        if (tid < 256) { red[tid] = mpart; red2[tid] = vpart; }
        __syncthreads();
        for (int st = 128; st > 0; st >>= 1) {
            if (tid < st) { red[tid] += red[tid + st]; red2[tid] += red2[tid + st]; }
            __syncthreads();
        }
        if (tid == 0) {
            float mean   = red[0]  + mean_b[s];
            float logvar = red2[0] + std_b[s];
            float eps = (s == 0) ? noise[RF + n] : gin[n];
            float nv = eps * expf(0.5f * logvar) + mean;
            gout[n] = nv;
            if (n >= NWIN - RF)
                out[3 * NWIN + s * RF + (n - (NWIN - RF))] = nv;
            if (s == NS - 1) {
                out[n] = nv;
                out[NWIN + n] = mean;
                out[2 * NWIN + n] = logvar;
            }
        }
    }
}

// ---------------- launcher ----------------
extern "C" void kernel_launch(void* const* d_in, const int* in_sizes, int n_in,
                              void* d_out, int out_size) {
    const float* mgc     = (const float*)d_in[0];
    const float* noise   = (const float*)d_in[1];
    const float* cond_w  = (const float*)d_in[2];
    const float* cond_b  = (const float*)d_in[3];
    const float* conv0_w = (const float*)d_in[4];
    const float* convs_w = (const float*)d_in[5];
    const float* conv_b  = (const float*)d_in[6];
    const float* ccw     = (const float*)d_in[7];
    const float* ccb     = (const float*)d_in[8];
    const float* pre_w   = (const float*)d_in[9];
    const float* pre_b   = (const float*)d_in[10];
    const float* mean_w  = (const float*)d_in[11];
    const float* mean_b  = (const float*)d_in[12];
    const float* std_w   = (const float*)d_in[13];
    const float* std_b   = (const float*)d_in[14];
    float* out = (float*)d_out;

    cudaFuncSetAttribute(k_stage, cudaFuncAttributeMaxDynamicSharedMemorySize, SMEM_BYTES);

    float* nA = nullptr; float* nB = nullptr;
    cudaGetSymbolAddress((void**)&nA, g_newA);
    cudaGetSymbolAddress((void**)&nB, g_newB);

    k_copy<<<(RF + 255) / 256, 256>>>(noise);
    k_cond<<<NWIN, 64>>>(mgc, cond_w, cond_b);

    for (int s = 0; s < NS; s++) {
        const float* gin = (s & 1) ? nA : nB;   // s=0 ignores gin
        float* gout      = (s & 1) ? nB : nA;
        k_stage<<<NWIN, 512, SMEM_BYTES>>>(s, noise, gin, gout,
                                           conv0_w, convs_w, conv_b,
                                           pre_w, pre_b, mean_w, mean_b,
                                           std_w, std_b, ccw, ccb, out);
    }
}